// round 1
// baseline (speedup 1.0000x reference)
#include <cuda_runtime.h>
#include <cuda_bf16.h>
#include <cstdint>

// Problem constants (fixed by the dataset)
#define NNODES 50000
#define NEDGES 800000
#define DF 96       // feature dim (in == out)
#define NF4 24      // DF / 4
#define KCHEB 3

// ---------------- scratch (device globals; no allocation allowed) -------------
__device__ __align__(16) float g_deg[NNODES];
__device__ __align__(16) float g_dis[NNODES];
__device__ __align__(16) float g_norm[NEDGES];
__device__ __align__(16) float g_T1[NNODES * DF];   // L x
__device__ __align__(16) float g_T2[NNODES * DF];   // L (L x)
__device__ __align__(16) float g_Wc[3 * DF * DF];   // combined weights [288][96]
__device__ __align__(16) float g_stats[2 * DF];     // sum, sumsq
__device__ __align__(16) float g_ab[2 * DF];        // per-channel scale, shift

// ---------------- zeroing (atomically-accumulated buffers) --------------------
__global__ void k_zero() {
    long stride = (long)gridDim.x * blockDim.x;
    long t0 = (long)blockIdx.x * blockDim.x + threadIdx.x;
    for (long i = t0; i < NNODES; i += stride) g_deg[i] = 0.f;
    for (long i = t0; i < (long)NNODES * DF; i += stride) { g_T1[i] = 0.f; g_T2[i] = 0.f; }
    if (t0 < 2 * DF) g_stats[t0] = 0.f;
}

// ---------------- degree / norm ----------------------------------------------
__global__ void k_deg(const int* __restrict__ ei) {
    int e = blockIdx.x * blockDim.x + threadIdx.x;
    if (e >= NEDGES) return;
    int r = ei[e], c = ei[NEDGES + e];
    if (r != c) atomicAdd(&g_deg[r], 1.0f);
}

__global__ void k_dis() {
    int i = blockIdx.x * blockDim.x + threadIdx.x;
    if (i >= NNODES) return;
    float d = g_deg[i];
    g_dis[i] = (d > 0.f) ? rsqrtf(d) : 0.f;
}

__global__ void k_norm(const int* __restrict__ ei) {
    int e = blockIdx.x * blockDim.x + threadIdx.x;
    if (e >= NEDGES) return;
    int r = ei[e], c = ei[NEDGES + e];
    g_norm[e] = (r != c) ? (-g_dis[r] * g_dis[c]) : 0.f;
}

// ---------------- sparse propagation: dst[col] += norm[e] * src[row] ----------
// One thread per (edge, float4 chunk): 24 chunks of 4 floats per edge.
// Scatter via 16B vector reduction (red.global.add.v4.f32, sm_90+).
__global__ void k_prop(const float* __restrict__ xin, int phase,
                       const int* __restrict__ ei) {
    int t = blockIdx.x * blockDim.x + threadIdx.x;
    if (t >= NEDGES * NF4) return;
    int e = t / NF4;
    int j = t - e * NF4;
    float nrm = g_norm[e];
    if (nrm == 0.f) return;
    int r = ei[e], c = ei[NEDGES + e];
    const float* src = (phase == 0) ? xin : g_T1;
    float* dst = (phase == 0) ? g_T1 : g_T2;
    float4 v = reinterpret_cast<const float4*>(src)[r * NF4 + j];
    float4* p = reinterpret_cast<float4*>(dst) + c * NF4 + j;
    asm volatile("red.global.add.v4.f32 [%0], {%1, %2, %3, %4};"
                 :: "l"(p), "f"(v.x * nrm), "f"(v.y * nrm),
                    "f"(v.z * nrm), "f"(v.w * nrm)
                 : "memory");
}

// ---------------- combined weight prep ----------------------------------------
// out = x@W0 + T1@W1 + (2*T2 - x)@W2  ==  x@(W0-W2) + T1@W1 + T2@(2*W2)
// g_Wc is [288][96] with K-block order: [x | T1 | T2]
__global__ void k_wprep(const float* __restrict__ W) {
    int idx = blockIdx.x * blockDim.x + threadIdx.x;
    if (idx >= 3 * DF * DF) return;
    int kg = idx / DF, c = idx - kg * DF;
    int m = kg / DF, i = kg - m * DF;
    float v;
    if (m == 0)      v = W[i * DF + c] - W[2 * DF * DF + i * DF + c];
    else if (m == 1) v = W[DF * DF + i * DF + c];
    else             v = 2.f * W[2 * DF * DF + i * DF + c];
    g_Wc[idx] = v;
}

// ---------------- fused GEMM: out[N,96] = [x|T1|T2][N,288] @ g_Wc[288,96] -----
// BM=64 rows, BN=96 cols, BK=16, 256 threads, 4x6 register tile per thread.
// (bias is omitted: a per-channel constant shift cancels exactly through BN.)
#define BM 64
#define BK 16
__global__ __launch_bounds__(256) void k_gemm(const float* __restrict__ x,
                                              float* __restrict__ out) {
    __shared__ float As[BK][BM + 1];
    __shared__ float Bs[BK][DF];
    int tid = threadIdx.x;
    int tr = tid >> 4;         // 0..15 -> rows tr*4 .. tr*4+3
    int tc = tid & 15;         // 0..15 -> cols tc*6 .. tc*6+5
    int row0 = blockIdx.x * BM;

    float acc[4][6];
#pragma unroll
    for (int i = 0; i < 4; i++)
#pragma unroll
        for (int j = 0; j < 6; j++) acc[i][j] = 0.f;

    const float* bases[3] = { x, g_T1, g_T2 };

    // A-tile loader mapping
    int a_row = tid >> 2;            // 0..63
    int a_kq  = (tid & 3) * 4;       // 0,4,8,12
    // B-tile loader mapping
    int b_kk = tid >> 4;             // 0..15
    int b_c0 = (tid & 15) * 6;       // 0,6,...,90

    for (int kc = 0; kc < 18; kc++) {
        const float* A = bases[kc / 6];
        int klocal = (kc % 6) * BK;

        float4 av = make_float4(0.f, 0.f, 0.f, 0.f);
        int r = row0 + a_row;
        if (r < NNODES)
            av = *reinterpret_cast<const float4*>(A + r * DF + klocal + a_kq);
        As[a_kq + 0][a_row] = av.x;
        As[a_kq + 1][a_row] = av.y;
        As[a_kq + 2][a_row] = av.z;
        As[a_kq + 3][a_row] = av.w;

        const float* Bp = g_Wc + (kc * BK + b_kk) * DF + b_c0;
#pragma unroll
        for (int j = 0; j < 6; j++) Bs[b_kk][b_c0 + j] = Bp[j];

        __syncthreads();
#pragma unroll
        for (int kk = 0; kk < BK; kk++) {
            float a[4], b[6];
#pragma unroll
            for (int i = 0; i < 4; i++) a[i] = As[kk][tr * 4 + i];
#pragma unroll
            for (int j = 0; j < 6; j++) b[j] = Bs[kk][tc * 6 + j];
#pragma unroll
            for (int i = 0; i < 4; i++)
#pragma unroll
                for (int j = 0; j < 6; j++) acc[i][j] += a[i] * b[j];
        }
        __syncthreads();
    }

#pragma unroll
    for (int i = 0; i < 4; i++) {
        int r = row0 + tr * 4 + i;
        if (r < NNODES) {
#pragma unroll
            for (int j = 0; j < 6; j++)
                out[r * DF + tc * 6 + j] = acc[i][j];
        }
    }
}

// ---------------- BatchNorm ----------------------------------------------------
__global__ void k_bnstats(const float* __restrict__ out) {
    __shared__ float ssum[DF], ssq[DF];
    int c = threadIdx.x % DF;
    int rg = threadIdx.x / DF;     // 0..2 (blockDim = 288)
    if (threadIdx.x < DF) { ssum[threadIdx.x] = 0.f; ssq[threadIdx.x] = 0.f; }
    __syncthreads();
    float s = 0.f, q = 0.f;
    for (int i = blockIdx.x * 3 + rg; i < NNODES; i += gridDim.x * 3) {
        float v = out[i * DF + c];
        s += v; q += v * v;
    }
    atomicAdd(&ssum[c], s);
    atomicAdd(&ssq[c], q);
    __syncthreads();
    if (threadIdx.x < DF) {
        atomicAdd(&g_stats[threadIdx.x], ssum[threadIdx.x]);
        atomicAdd(&g_stats[DF + threadIdx.x], ssq[threadIdx.x]);
    }
}

__global__ void k_bnfin(const float* __restrict__ gamma,
                        const float* __restrict__ beta) {
    int c = threadIdx.x;
    if (c >= DF) return;
    float mean = g_stats[c] * (1.0f / NNODES);
    float var  = g_stats[DF + c] * (1.0f / NNODES) - mean * mean;
    float a = gamma[c] * rsqrtf(var + 1e-5f);
    g_ab[c] = a;
    g_ab[DF + c] = beta[c] - mean * a;
}

__global__ void k_bnapply(float* __restrict__ out) {
    int t = blockIdx.x * blockDim.x + threadIdx.x;
    if (t >= NNODES * NF4) return;
    int j = t % NF4;
    int c0 = j * 4;
    float4 v = reinterpret_cast<float4*>(out)[t];
    v.x = v.x * g_ab[c0 + 0] + g_ab[DF + c0 + 0];
    v.y = v.y * g_ab[c0 + 1] + g_ab[DF + c0 + 1];
    v.z = v.z * g_ab[c0 + 2] + g_ab[DF + c0 + 2];
    v.w = v.w * g_ab[c0 + 3] + g_ab[DF + c0 + 3];
    reinterpret_cast<float4*>(out)[t] = v;
}

// ---------------- launch -------------------------------------------------------
extern "C" void kernel_launch(void* const* d_in, const int* in_sizes, int n_in,
                              void* d_out, int out_size) {
    const float* x     = (const float*)d_in[0];  // [N, 96]
    const int*   ei    = (const int*)  d_in[1];  // [2, E]
    const float* W     = (const float*)d_in[2];  // [3, 96, 96]
    // d_in[3] = bias: provably cancels through BatchNorm -> unused
    const float* gamma = (const float*)d_in[4];  // [96]
    const float* beta  = (const float*)d_in[5];  // [96]
    float* out = (float*)d_out;                  // [N, 96] fp32

    k_zero<<<2048, 256>>>();
    k_deg <<<(NEDGES + 255) / 256, 256>>>(ei);
    k_dis <<<(NNODES + 255) / 256, 256>>>();
    k_norm<<<(NEDGES + 255) / 256, 256>>>(ei);

    const int propThreads = NEDGES * NF4;             // 19.2M
    k_prop<<<(propThreads + 191) / 192, 192>>>(x, 0, ei);   // T1 = L x
    k_prop<<<(propThreads + 191) / 192, 192>>>(x, 1, ei);   // T2 = L T1

    k_wprep<<<(3 * DF * DF + 255) / 256, 256>>>(W);
    k_gemm <<<(NNODES + BM - 1) / BM, 256>>>(x, out);

    k_bnstats<<<160, 288>>>(out);
    k_bnfin  <<<1, DF>>>(gamma, beta);
    k_bnapply<<<(NNODES * NF4 + 255) / 256, 256>>>(out);
}

// round 4
// speedup vs baseline: 1.0241x; 1.0241x over previous
#include <cuda_runtime.h>
#include <cuda_bf16.h>
#include <cstdint>

#define NNODES 50000
#define NEDGES 800000
#define DF 96
#define NF4 24

// ---------------- scratch ------------------------------------------------------
__device__ __align__(16) float g_deg[NNODES];
__device__ __align__(16) float g_dis[NNODES];
__device__ __align__(16) int   g_cnt[NNODES];        // in-degree / fill cursor
__device__ __align__(16) int   g_rowptr[NNODES + 1]; // CSR by destination
__device__ __align__(16) int   g_csr_src[NEDGES];
__device__ __align__(16) float g_csr_w[NEDGES];
__device__ __align__(16) float g_T1[NNODES * DF];
__device__ __align__(16) float g_T2[NNODES * DF];
__device__ __align__(16) float g_Wc[3 * DF * DF];    // [288][96]
__device__ __align__(16) float g_stats[2 * DF];
__device__ __align__(16) float g_ab[2 * DF];

// ---------------- init ---------------------------------------------------------
__global__ void k_init() {
    int stride = gridDim.x * blockDim.x;
    int t0 = blockIdx.x * blockDim.x + threadIdx.x;
    for (int i = t0; i < NNODES; i += stride) { g_deg[i] = 0.f; g_cnt[i] = 0; }
    if (t0 < 2 * DF) g_stats[t0] = 0.f;
}

// out-degree (rows) for the norm, in-degree histogram (cols) for CSR
__global__ void k_count(const int* __restrict__ ei) {
    int e = blockIdx.x * blockDim.x + threadIdx.x;
    if (e >= NEDGES) return;
    int r = ei[e], c = ei[NEDGES + e];
    if (r != c) {
        atomicAdd(&g_deg[r], 1.0f);
        atomicAdd(&g_cnt[c], 1);
    }
}

__global__ void k_dis() {
    int i = blockIdx.x * blockDim.x + threadIdx.x;
    if (i >= NNODES) return;
    float d = g_deg[i];
    g_dis[i] = (d > 0.f) ? rsqrtf(d) : 0.f;
}

// exclusive scan of g_cnt -> g_rowptr; also re-zeroes g_cnt for the fill pass
#define SCAN_T 1024
#define SCHUNK 49   // 1024*49 >= 50000
__global__ void k_scan() {
    __shared__ int part[SCAN_T];
    int t = threadIdx.x;
    int lo = t * SCHUNK;
    int hi = min(lo + SCHUNK, NNODES);
    int s = 0;
    for (int i = lo; i < hi; i++) s += g_cnt[i];
    part[t] = s;
    __syncthreads();
    for (int off = 1; off < SCAN_T; off <<= 1) {
        int v = (t >= off) ? part[t - off] : 0;
        __syncthreads();
        part[t] += v;
        __syncthreads();
    }
    int run = (t == 0) ? 0 : part[t - 1];
    for (int i = lo; i < hi; i++) {
        int c = g_cnt[i];
        g_rowptr[i] = run;
        run += c;
        g_cnt[i] = 0;
    }
    if (t == SCAN_T - 1) g_rowptr[NNODES] = run;
}

__global__ void k_fill(const int* __restrict__ ei) {
    int e = blockIdx.x * blockDim.x + threadIdx.x;
    if (e >= NEDGES) return;
    int r = ei[e], c = ei[NEDGES + e];
    if (r == c) return;
    int pos = g_rowptr[c] + atomicAdd(&g_cnt[c], 1);
    g_csr_src[pos] = r;
    g_csr_w[pos] = -g_dis[r] * g_dis[c];
}

// ---------------- pull-mode propagation ----------------------------------------
// One warp per destination node; each lane owns features {lane, lane+32, lane+64}.
// phase 0: T1 = L x     phase 1: T2 = L T1
// NOTE: src/dst selected DEVICE-SIDE. Passing __device__ globals as host-side
// kernel args silently writes host memory via ATS on GB300 (R2/R3 bug).
__global__ __launch_bounds__(256) void k_pull(int phase,
                                              const float* __restrict__ x) {
    const float* src = (phase == 0) ? x : g_T1;
    float* dst = (phase == 0) ? g_T1 : g_T2;
    int w = (blockIdx.x * blockDim.x + threadIdx.x) >> 5;
    int lane = threadIdx.x & 31;
    if (w >= NNODES) return;
    int s = g_rowptr[w], e = g_rowptr[w + 1];
    float a0 = 0.f, a1 = 0.f, a2 = 0.f;
    int i = s;
    for (; i + 2 <= e; i += 2) {
        int r0 = g_csr_src[i], r1 = g_csr_src[i + 1];
        float w0 = g_csr_w[i], w1 = g_csr_w[i + 1];
        const float* p0 = src + r0 * DF + lane;
        const float* p1 = src + r1 * DF + lane;
        a0 += w0 * p0[0];  a1 += w0 * p0[32];  a2 += w0 * p0[64];
        a0 += w1 * p1[0];  a1 += w1 * p1[32];  a2 += w1 * p1[64];
    }
    if (i < e) {
        int r = g_csr_src[i];
        float ww = g_csr_w[i];
        const float* p = src + r * DF + lane;
        a0 += ww * p[0];  a1 += ww * p[32];  a2 += ww * p[64];
    }
    dst[w * DF + lane] = a0;
    dst[w * DF + 32 + lane] = a1;
    dst[w * DF + 64 + lane] = a2;
}

// ---------------- combined weights: [x | T1 | T2] blocks -----------------------
// out = x@(W0-W2) + T1@W1 + T2@(2*W2); bias cancels through BN.
__global__ void k_wprep(const float* __restrict__ W) {
    int idx = blockIdx.x * blockDim.x + threadIdx.x;
    if (idx >= 3 * DF * DF) return;
    int kg = idx / DF, c = idx - kg * DF;
    int m = kg / DF, i = kg - m * DF;
    float v;
    if (m == 0)      v = W[i * DF + c] - W[2 * DF * DF + i * DF + c];
    else if (m == 1) v = W[DF * DF + i * DF + c];
    else             v = 2.f * W[2 * DF * DF + i * DF + c];
    g_Wc[idx] = v;
}

// ---------------- fused GEMM (EXACT R1 version, known-good) --------------------
#define BM 64
#define BK 16
__global__ __launch_bounds__(256) void k_gemm(const float* __restrict__ x,
                                              float* __restrict__ out) {
    __shared__ float As[BK][BM + 1];
    __shared__ float Bs[BK][DF];
    int tid = threadIdx.x;
    int tr = tid >> 4;         // 0..15 -> rows tr*4 .. tr*4+3
    int tc = tid & 15;         // 0..15 -> cols tc*6 .. tc*6+5
    int row0 = blockIdx.x * BM;

    float acc[4][6];
#pragma unroll
    for (int i = 0; i < 4; i++)
#pragma unroll
        for (int j = 0; j < 6; j++) acc[i][j] = 0.f;

    const float* bases[3] = { x, g_T1, g_T2 };

    int a_row = tid >> 2;            // 0..63
    int a_kq  = (tid & 3) * 4;       // 0,4,8,12
    int b_kk = tid >> 4;             // 0..15
    int b_c0 = (tid & 15) * 6;       // 0,6,...,90

    for (int kc = 0; kc < 18; kc++) {
        const float* A = bases[kc / 6];
        int klocal = (kc % 6) * BK;

        float4 av = make_float4(0.f, 0.f, 0.f, 0.f);
        int r = row0 + a_row;
        if (r < NNODES)
            av = *reinterpret_cast<const float4*>(A + r * DF + klocal + a_kq);
        As[a_kq + 0][a_row] = av.x;
        As[a_kq + 1][a_row] = av.y;
        As[a_kq + 2][a_row] = av.z;
        As[a_kq + 3][a_row] = av.w;

        const float* Bp = g_Wc + (kc * BK + b_kk) * DF + b_c0;
#pragma unroll
        for (int j = 0; j < 6; j++) Bs[b_kk][b_c0 + j] = Bp[j];

        __syncthreads();
#pragma unroll
        for (int kk = 0; kk < BK; kk++) {
            float a[4], b[6];
#pragma unroll
            for (int i = 0; i < 4; i++) a[i] = As[kk][tr * 4 + i];
#pragma unroll
            for (int j = 0; j < 6; j++) b[j] = Bs[kk][tc * 6 + j];
#pragma unroll
            for (int i = 0; i < 4; i++)
#pragma unroll
                for (int j = 0; j < 6; j++) acc[i][j] += a[i] * b[j];
        }
        __syncthreads();
    }

#pragma unroll
    for (int i = 0; i < 4; i++) {
        int r = row0 + tr * 4 + i;
        if (r < NNODES) {
#pragma unroll
            for (int j = 0; j < 6; j++)
                out[r * DF + tc * 6 + j] = acc[i][j];
        }
    }
}

// ---------------- BatchNorm (EXACT R1 version, known-good) ---------------------
__global__ void k_bnstats(const float* __restrict__ out) {
    __shared__ float ssum[DF], ssq[DF];
    int c = threadIdx.x % DF;
    int rg = threadIdx.x / DF;     // 0..2 (blockDim = 288)
    if (threadIdx.x < DF) { ssum[threadIdx.x] = 0.f; ssq[threadIdx.x] = 0.f; }
    __syncthreads();
    float s = 0.f, q = 0.f;
    for (int i = blockIdx.x * 3 + rg; i < NNODES; i += gridDim.x * 3) {
        float v = out[i * DF + c];
        s += v; q += v * v;
    }
    atomicAdd(&ssum[c], s);
    atomicAdd(&ssq[c], q);
    __syncthreads();
    if (threadIdx.x < DF) {
        atomicAdd(&g_stats[threadIdx.x], ssum[threadIdx.x]);
        atomicAdd(&g_stats[DF + threadIdx.x], ssq[threadIdx.x]);
    }
}

__global__ void k_bnfin(const float* __restrict__ gamma,
                        const float* __restrict__ beta) {
    int c = threadIdx.x;
    if (c >= DF) return;
    float mean = g_stats[c] * (1.0f / NNODES);
    float var  = g_stats[DF + c] * (1.0f / NNODES) - mean * mean;
    float a = gamma[c] * rsqrtf(var + 1e-5f);
    g_ab[c] = a;
    g_ab[DF + c] = beta[c] - mean * a;
}

__global__ void k_bnapply(float* __restrict__ out) {
    int t = blockIdx.x * blockDim.x + threadIdx.x;
    if (t >= NNODES * NF4) return;
    int j = t % NF4;
    int c0 = j * 4;
    float4 v = reinterpret_cast<float4*>(out)[t];
    v.x = v.x * g_ab[c0 + 0] + g_ab[DF + c0 + 0];
    v.y = v.y * g_ab[c0 + 1] + g_ab[DF + c0 + 1];
    v.z = v.z * g_ab[c0 + 2] + g_ab[DF + c0 + 2];
    v.w = v.w * g_ab[c0 + 3] + g_ab[DF + c0 + 3];
    reinterpret_cast<float4*>(out)[t] = v;
}

// ---------------- launch -------------------------------------------------------
extern "C" void kernel_launch(void* const* d_in, const int* in_sizes, int n_in,
                              void* d_out, int out_size) {
    const float* x     = (const float*)d_in[0];
    const int*   ei    = (const int*)  d_in[1];
    const float* W     = (const float*)d_in[2];
    const float* gamma = (const float*)d_in[4];
    const float* beta  = (const float*)d_in[5];
    float* out = (float*)d_out;

    k_init <<<128, 512>>>();
    k_count<<<(NEDGES + 255) / 256, 256>>>(ei);
    k_dis  <<<(NNODES + 255) / 256, 256>>>();
    k_scan <<<1, SCAN_T>>>();
    k_fill <<<(NEDGES + 255) / 256, 256>>>(ei);

    const int pullBlocks = (NNODES * 32 + 255) / 256;
    k_pull<<<pullBlocks, 256>>>(0, x);   // T1 = L x
    k_pull<<<pullBlocks, 256>>>(1, x);   // T2 = L T1

    k_wprep<<<(3 * DF * DF + 255) / 256, 256>>>(W);
    k_gemm <<<(NNODES + BM - 1) / BM, 256>>>(x, out);

    k_bnstats<<<160, 288>>>(out);
    k_bnfin  <<<1, DF>>>(gamma, beta);
    k_bnapply<<<(NNODES * NF4 + 255) / 256, 256>>>(out);
}

// round 5
// speedup vs baseline: 1.3208x; 1.2897x over previous
#include <cuda_runtime.h>
#include <cuda_bf16.h>
#include <cstdint>

#define NNODES 50000
#define NEDGES 800000
#define DF 96
#define NF4 24

// ---------------- scratch ------------------------------------------------------
__device__ __align__(16) float g_deg[NNODES];
__device__ __align__(16) float g_dis[NNODES];
__device__ __align__(16) int   g_cnt[NNODES];        // in-degree / fill cursor
__device__ __align__(16) int   g_rowptr[NNODES + 1]; // CSR by destination
__device__ __align__(16) int   g_csr_src[NEDGES];
__device__ __align__(16) float g_csr_w[NEDGES];
__device__ __align__(16) float g_T1[NNODES * DF];
__device__ __align__(16) float g_T2[NNODES * DF];
__device__ __align__(16) float g_Wc[3 * DF * DF];    // [288][96]
__device__ __align__(16) float g_stats[2 * DF];
__device__ __align__(16) float g_ab[2 * DF];

// grid-scan scratch
#define SBLK 512
#define NBLK ((NNODES + SBLK - 1) / SBLK)   // 98
__device__ int g_bsum[NBLK];
__device__ int g_boff[NBLK];

// ---------------- init ---------------------------------------------------------
__global__ void k_init() {
    int stride = gridDim.x * blockDim.x;
    int t0 = blockIdx.x * blockDim.x + threadIdx.x;
    for (int i = t0; i < NNODES; i += stride) { g_deg[i] = 0.f; g_cnt[i] = 0; }
    if (t0 < 2 * DF) g_stats[t0] = 0.f;
}

// out-degree (rows) for the norm, in-degree histogram (cols) for CSR
__global__ void k_count(const int* __restrict__ ei) {
    int e = blockIdx.x * blockDim.x + threadIdx.x;
    if (e >= NEDGES) return;
    int r = ei[e], c = ei[NEDGES + e];
    if (r != c) {
        atomicAdd(&g_deg[r], 1.0f);
        atomicAdd(&g_cnt[c], 1);
    }
}

__global__ void k_dis() {
    int i = blockIdx.x * blockDim.x + threadIdx.x;
    if (i >= NNODES) return;
    float d = g_deg[i];
    g_dis[i] = (d > 0.f) ? rsqrtf(d) : 0.f;
}

// ---------------- decoupled grid scan (replaces 70us single-block scan) --------
// Stage 1: per-block exclusive scan of g_cnt -> g_rowptr (partial), totals -> g_bsum
__global__ __launch_bounds__(SBLK) void k_scan_blk() {
    __shared__ int wsum[SBLK / 32];
    int i = blockIdx.x * SBLK + threadIdx.x;
    int lane = threadIdx.x & 31;
    int wid = threadIdx.x >> 5;
    int v = (i < NNODES) ? g_cnt[i] : 0;

    // warp inclusive scan
    int incl = v;
#pragma unroll
    for (int d = 1; d < 32; d <<= 1) {
        int t = __shfl_up_sync(0xffffffffu, incl, d);
        if (lane >= d) incl += t;
    }
    if (lane == 31) wsum[wid] = incl;
    __syncthreads();
    if (wid == 0) {
        int ws = (lane < SBLK / 32) ? wsum[lane] : 0;
        int wincl = ws;
#pragma unroll
        for (int d = 1; d < SBLK / 32; d <<= 1) {
            int t = __shfl_up_sync(0xffffffffu, wincl, d);
            if (lane >= d) wincl += t;
        }
        if (lane < SBLK / 32) wsum[lane] = wincl - ws;   // exclusive warp offsets
        if (lane == SBLK / 32 - 1) g_bsum[blockIdx.x] = wincl;
    }
    __syncthreads();
    if (i < NNODES) g_rowptr[i] = (incl - v) + wsum[wid];
}

// Stage 2: single small block scans the 98 block totals (exclusive) -> g_boff
__global__ void k_scan_top() {
    __shared__ int wsum[4];
    int t = threadIdx.x;          // 128 threads
    int lane = t & 31;
    int wid = t >> 5;
    int v = (t < NBLK) ? g_bsum[t] : 0;
    int incl = v;
#pragma unroll
    for (int d = 1; d < 32; d <<= 1) {
        int x = __shfl_up_sync(0xffffffffu, incl, d);
        if (lane >= d) incl += x;
    }
    if (lane == 31) wsum[wid] = incl;
    __syncthreads();
    if (wid == 0 && lane < 4) {
        int ws = wsum[lane];
        int wincl = ws;
#pragma unroll
        for (int d = 1; d < 4; d <<= 1) {
            int x = __shfl_up_sync(0x0000000fu, wincl, d);
            if (lane >= d) wincl += x;
        }
        wsum[lane] = wincl - ws;
        if (lane == 3) g_rowptr[NNODES] = wincl;   // total edge count
    }
    __syncthreads();
    if (t < NBLK) g_boff[t] = (incl - v) + wsum[wid];
}

// Stage 3: add block offsets; re-zero g_cnt for the fill pass
__global__ void k_scan_add() {
    int i = blockIdx.x * blockDim.x + threadIdx.x;
    if (i >= NNODES) return;
    g_rowptr[i] += g_boff[i >> 9];   // SBLK = 512 = 1<<9
    g_cnt[i] = 0;
}

__global__ void k_fill(const int* __restrict__ ei) {
    int e = blockIdx.x * blockDim.x + threadIdx.x;
    if (e >= NEDGES) return;
    int r = ei[e], c = ei[NEDGES + e];
    if (r == c) return;
    int pos = g_rowptr[c] + atomicAdd(&g_cnt[c], 1);
    g_csr_src[pos] = r;
    g_csr_w[pos] = -g_dis[r] * g_dis[c];
}

// ---------------- pull-mode propagation ----------------------------------------
// One warp per destination node; each lane owns features {lane, lane+32, lane+64}.
// phase 0: T1 = L x     phase 1: T2 = L T1
// NOTE: src/dst selected DEVICE-SIDE (host-side &__device__ global is the R2 bug).
__global__ __launch_bounds__(256) void k_pull(int phase,
                                              const float* __restrict__ x) {
    const float* src = (phase == 0) ? x : g_T1;
    float* dst = (phase == 0) ? g_T1 : g_T2;
    int w = (blockIdx.x * blockDim.x + threadIdx.x) >> 5;
    int lane = threadIdx.x & 31;
    if (w >= NNODES) return;
    int s = g_rowptr[w], e = g_rowptr[w + 1];
    float a0 = 0.f, a1 = 0.f, a2 = 0.f;
    int i = s;
    for (; i + 2 <= e; i += 2) {
        int r0 = g_csr_src[i], r1 = g_csr_src[i + 1];
        float w0 = g_csr_w[i], w1 = g_csr_w[i + 1];
        const float* p0 = src + r0 * DF + lane;
        const float* p1 = src + r1 * DF + lane;
        a0 += w0 * p0[0];  a1 += w0 * p0[32];  a2 += w0 * p0[64];
        a0 += w1 * p1[0];  a1 += w1 * p1[32];  a2 += w1 * p1[64];
    }
    if (i < e) {
        int r = g_csr_src[i];
        float ww = g_csr_w[i];
        const float* p = src + r * DF + lane;
        a0 += ww * p[0];  a1 += ww * p[32];  a2 += ww * p[64];
    }
    dst[w * DF + lane] = a0;
    dst[w * DF + 32 + lane] = a1;
    dst[w * DF + 64 + lane] = a2;
}

// ---------------- combined weights: [x | T1 | T2] blocks -----------------------
// out = x@(W0-W2) + T1@W1 + T2@(2*W2); bias cancels through BN.
__global__ void k_wprep(const float* __restrict__ W) {
    int idx = blockIdx.x * blockDim.x + threadIdx.x;
    if (idx >= 3 * DF * DF) return;
    int kg = idx / DF, c = idx - kg * DF;
    int m = kg / DF, i = kg - m * DF;
    float v;
    if (m == 0)      v = W[i * DF + c] - W[2 * DF * DF + i * DF + c];
    else if (m == 1) v = W[DF * DF + i * DF + c];
    else             v = 2.f * W[2 * DF * DF + i * DF + c];
    g_Wc[idx] = v;
}

// ---------------- fused GEMM (known-good) --------------------------------------
#define BM 64
#define BK 16
__global__ __launch_bounds__(256) void k_gemm(const float* __restrict__ x,
                                              float* __restrict__ out) {
    __shared__ float As[BK][BM + 1];
    __shared__ float Bs[BK][DF];
    int tid = threadIdx.x;
    int tr = tid >> 4;
    int tc = tid & 15;
    int row0 = blockIdx.x * BM;

    float acc[4][6];
#pragma unroll
    for (int i = 0; i < 4; i++)
#pragma unroll
        for (int j = 0; j < 6; j++) acc[i][j] = 0.f;

    const float* bases[3] = { x, g_T1, g_T2 };

    int a_row = tid >> 2;
    int a_kq  = (tid & 3) * 4;
    int b_kk = tid >> 4;
    int b_c0 = (tid & 15) * 6;

    for (int kc = 0; kc < 18; kc++) {
        const float* A = bases[kc / 6];
        int klocal = (kc % 6) * BK;

        float4 av = make_float4(0.f, 0.f, 0.f, 0.f);
        int r = row0 + a_row;
        if (r < NNODES)
            av = *reinterpret_cast<const float4*>(A + r * DF + klocal + a_kq);
        As[a_kq + 0][a_row] = av.x;
        As[a_kq + 1][a_row] = av.y;
        As[a_kq + 2][a_row] = av.z;
        As[a_kq + 3][a_row] = av.w;

        const float* Bp = g_Wc + (kc * BK + b_kk) * DF + b_c0;
#pragma unroll
        for (int j = 0; j < 6; j++) Bs[b_kk][b_c0 + j] = Bp[j];

        __syncthreads();
#pragma unroll
        for (int kk = 0; kk < BK; kk++) {
            float a[4], b[6];
#pragma unroll
            for (int i = 0; i < 4; i++) a[i] = As[kk][tr * 4 + i];
#pragma unroll
            for (int j = 0; j < 6; j++) b[j] = Bs[kk][tc * 6 + j];
#pragma unroll
            for (int i = 0; i < 4; i++)
#pragma unroll
                for (int j = 0; j < 6; j++) acc[i][j] += a[i] * b[j];
        }
        __syncthreads();
    }

#pragma unroll
    for (int i = 0; i < 4; i++) {
        int r = row0 + tr * 4 + i;
        if (r < NNODES) {
#pragma unroll
            for (int j = 0; j < 6; j++)
                out[r * DF + tc * 6 + j] = acc[i][j];
        }
    }
}

// ---------------- BatchNorm (known-good) ---------------------------------------
__global__ void k_bnstats(const float* __restrict__ out) {
    __shared__ float ssum[DF], ssq[DF];
    int c = threadIdx.x % DF;
    int rg = threadIdx.x / DF;
    if (threadIdx.x < DF) { ssum[threadIdx.x] = 0.f; ssq[threadIdx.x] = 0.f; }
    __syncthreads();
    float s = 0.f, q = 0.f;
    for (int i = blockIdx.x * 3 + rg; i < NNODES; i += gridDim.x * 3) {
        float v = out[i * DF + c];
        s += v; q += v * v;
    }
    atomicAdd(&ssum[c], s);
    atomicAdd(&ssq[c], q);
    __syncthreads();
    if (threadIdx.x < DF) {
        atomicAdd(&g_stats[threadIdx.x], ssum[threadIdx.x]);
        atomicAdd(&g_stats[DF + threadIdx.x], ssq[threadIdx.x]);
    }
}

__global__ void k_bnfin(const float* __restrict__ gamma,
                        const float* __restrict__ beta) {
    int c = threadIdx.x;
    if (c >= DF) return;
    float mean = g_stats[c] * (1.0f / NNODES);
    float var  = g_stats[DF + c] * (1.0f / NNODES) - mean * mean;
    float a = gamma[c] * rsqrtf(var + 1e-5f);
    g_ab[c] = a;
    g_ab[DF + c] = beta[c] - mean * a;
}

__global__ void k_bnapply(float* __restrict__ out) {
    int t = blockIdx.x * blockDim.x + threadIdx.x;
    if (t >= NNODES * NF4) return;
    int j = t % NF4;
    int c0 = j * 4;
    float4 v = reinterpret_cast<float4*>(out)[t];
    v.x = v.x * g_ab[c0 + 0] + g_ab[DF + c0 + 0];
    v.y = v.y * g_ab[c0 + 1] + g_ab[DF + c0 + 1];
    v.z = v.z * g_ab[c0 + 2] + g_ab[DF + c0 + 2];
    v.w = v.w * g_ab[c0 + 3] + g_ab[DF + c0 + 3];
    reinterpret_cast<float4*>(out)[t] = v;
}

// ---------------- launch -------------------------------------------------------
extern "C" void kernel_launch(void* const* d_in, const int* in_sizes, int n_in,
                              void* d_out, int out_size) {
    const float* x     = (const float*)d_in[0];
    const int*   ei    = (const int*)  d_in[1];
    const float* W     = (const float*)d_in[2];
    const float* gamma = (const float*)d_in[4];
    const float* beta  = (const float*)d_in[5];
    float* out = (float*)d_out;

    k_init <<<128, 512>>>();
    k_count<<<(NEDGES + 255) / 256, 256>>>(ei);
    k_dis  <<<(NNODES + 255) / 256, 256>>>();

    k_scan_blk<<<NBLK, SBLK>>>();
    k_scan_top<<<1, 128>>>();
    k_scan_add<<<(NNODES + 255) / 256, 256>>>();

    k_fill <<<(NEDGES + 255) / 256, 256>>>(ei);

    const int pullBlocks = (NNODES * 32 + 255) / 256;
    k_pull<<<pullBlocks, 256>>>(0, x);   // T1 = L x
    k_pull<<<pullBlocks, 256>>>(1, x);   // T2 = L T1

    k_wprep<<<(3 * DF * DF + 255) / 256, 256>>>(W);
    k_gemm <<<(NNODES + BM - 1) / BM, 256>>>(x, out);

    k_bnstats<<<160, 288>>>(out);
    k_bnfin  <<<1, DF>>>(gamma, beta);
    k_bnapply<<<(NNODES * NF4 + 255) / 256, 256>>>(out);
}

// round 6
// speedup vs baseline: 1.4808x; 1.1211x over previous
#include <cuda_runtime.h>
#include <cuda_bf16.h>
#include <cstdint>

#define NNODES 50000
#define NEDGES 800000
#define DF 96
#define NF4 24

// ---------------- scratch ------------------------------------------------------
__device__ __align__(16) float g_deg[NNODES];
__device__ __align__(16) float g_dis[NNODES];
__device__ __align__(16) int   g_cnt[NNODES];        // in-degree / fill cursor
__device__ __align__(16) int   g_rowptr[NNODES + 1]; // CSR by destination
__device__ __align__(16) int   g_csr_src[NEDGES];
__device__ __align__(16) float g_csr_w[NEDGES];
__device__ __align__(16) float g_T1[NNODES * DF];
__device__ __align__(16) float g_T2[NNODES * DF];
__device__ __align__(16) float g_Wc[3 * DF * DF];    // [288][96]
__device__ __align__(16) float g_stats[2 * DF];
__device__ __align__(16) float g_ab[2 * DF];

// grid-scan scratch
#define SBLK 512
#define NBLK ((NNODES + SBLK - 1) / SBLK)   // 98
__device__ int g_bsum[NBLK];
__device__ int g_boff[NBLK];

// ---------------- init ---------------------------------------------------------
__global__ void k_init() {
    int stride = gridDim.x * blockDim.x;
    int t0 = blockIdx.x * blockDim.x + threadIdx.x;
    for (int i = t0; i < NNODES; i += stride) { g_deg[i] = 0.f; g_cnt[i] = 0; }
    if (t0 < 2 * DF) g_stats[t0] = 0.f;
}

__global__ void k_count(const int* __restrict__ ei) {
    int e = blockIdx.x * blockDim.x + threadIdx.x;
    if (e >= NEDGES) return;
    int r = ei[e], c = ei[NEDGES + e];
    if (r != c) {
        atomicAdd(&g_deg[r], 1.0f);
        atomicAdd(&g_cnt[c], 1);
    }
}

__global__ void k_dis() {
    int i = blockIdx.x * blockDim.x + threadIdx.x;
    if (i >= NNODES) return;
    float d = g_deg[i];
    g_dis[i] = (d > 0.f) ? rsqrtf(d) : 0.f;
}

// ---------------- decoupled grid scan ------------------------------------------
__global__ __launch_bounds__(SBLK) void k_scan_blk() {
    __shared__ int wsum[SBLK / 32];
    int i = blockIdx.x * SBLK + threadIdx.x;
    int lane = threadIdx.x & 31;
    int wid = threadIdx.x >> 5;
    int v = (i < NNODES) ? g_cnt[i] : 0;

    int incl = v;
#pragma unroll
    for (int d = 1; d < 32; d <<= 1) {
        int t = __shfl_up_sync(0xffffffffu, incl, d);
        if (lane >= d) incl += t;
    }
    if (lane == 31) wsum[wid] = incl;
    __syncthreads();
    if (wid == 0) {
        int ws = (lane < SBLK / 32) ? wsum[lane] : 0;
        int wincl = ws;
#pragma unroll
        for (int d = 1; d < SBLK / 32; d <<= 1) {
            int t = __shfl_up_sync(0xffffffffu, wincl, d);
            if (lane >= d) wincl += t;
        }
        if (lane < SBLK / 32) wsum[lane] = wincl - ws;
        if (lane == SBLK / 32 - 1) g_bsum[blockIdx.x] = wincl;
    }
    __syncthreads();
    if (i < NNODES) g_rowptr[i] = (incl - v) + wsum[wid];
}

__global__ void k_scan_top() {
    __shared__ int wsum[4];
    int t = threadIdx.x;          // 128 threads
    int lane = t & 31;
    int wid = t >> 5;
    int v = (t < NBLK) ? g_bsum[t] : 0;
    int incl = v;
#pragma unroll
    for (int d = 1; d < 32; d <<= 1) {
        int x = __shfl_up_sync(0xffffffffu, incl, d);
        if (lane >= d) incl += x;
    }
    if (lane == 31) wsum[wid] = incl;
    __syncthreads();
    if (wid == 0 && lane < 4) {
        int ws = wsum[lane];
        int wincl = ws;
#pragma unroll
        for (int d = 1; d < 4; d <<= 1) {
            int x = __shfl_up_sync(0x0000000fu, wincl, d);
            if (lane >= d) wincl += x;
        }
        wsum[lane] = wincl - ws;
        if (lane == 3) g_rowptr[NNODES] = wincl;
    }
    __syncthreads();
    if (t < NBLK) g_boff[t] = (incl - v) + wsum[wid];
}

__global__ void k_scan_add() {
    int i = blockIdx.x * blockDim.x + threadIdx.x;
    if (i >= NNODES) return;
    g_rowptr[i] += g_boff[i >> 9];   // SBLK = 512
    g_cnt[i] = 0;
}

__global__ void k_fill(const int* __restrict__ ei) {
    int e = blockIdx.x * blockDim.x + threadIdx.x;
    if (e >= NEDGES) return;
    int r = ei[e], c = ei[NEDGES + e];
    if (r == c) return;
    int pos = g_rowptr[c] + atomicAdd(&g_cnt[c], 1);
    g_csr_src[pos] = r;
    g_csr_w[pos] = -g_dis[r] * g_dis[c];
}

// ---------------- pull-mode propagation (known-good) ----------------------------
__global__ __launch_bounds__(256) void k_pull(int phase,
                                              const float* __restrict__ x) {
    const float* src = (phase == 0) ? x : g_T1;
    float* dst = (phase == 0) ? g_T1 : g_T2;
    int w = (blockIdx.x * blockDim.x + threadIdx.x) >> 5;
    int lane = threadIdx.x & 31;
    if (w >= NNODES) return;
    int s = g_rowptr[w], e = g_rowptr[w + 1];
    float a0 = 0.f, a1 = 0.f, a2 = 0.f;
    int i = s;
    for (; i + 2 <= e; i += 2) {
        int r0 = g_csr_src[i], r1 = g_csr_src[i + 1];
        float w0 = g_csr_w[i], w1 = g_csr_w[i + 1];
        const float* p0 = src + r0 * DF + lane;
        const float* p1 = src + r1 * DF + lane;
        a0 += w0 * p0[0];  a1 += w0 * p0[32];  a2 += w0 * p0[64];
        a0 += w1 * p1[0];  a1 += w1 * p1[32];  a2 += w1 * p1[64];
    }
    if (i < e) {
        int r = g_csr_src[i];
        float ww = g_csr_w[i];
        const float* p = src + r * DF + lane;
        a0 += ww * p[0];  a1 += ww * p[32];  a2 += ww * p[64];
    }
    dst[w * DF + lane] = a0;
    dst[w * DF + 32 + lane] = a1;
    dst[w * DF + 64 + lane] = a2;
}

// ---------------- combined weights ---------------------------------------------
__global__ void k_wprep(const float* __restrict__ W) {
    int idx = blockIdx.x * blockDim.x + threadIdx.x;
    if (idx >= 3 * DF * DF) return;
    int kg = idx / DF, c = idx - kg * DF;
    int m = kg / DF, i = kg - m * DF;
    float v;
    if (m == 0)      v = W[i * DF + c] - W[2 * DF * DF + i * DF + c];
    else if (m == 1) v = W[DF * DF + i * DF + c];
    else             v = 2.f * W[2 * DF * DF + i * DF + c];
    g_Wc[idx] = v;
}

// ---------------- FFMA2 helpers ------------------------------------------------
typedef unsigned long long u64t;
__device__ __forceinline__ u64t dup2(float v) {
    u64t r;
    asm("mov.b64 %0, {%1, %1};" : "=l"(r) : "f"(v));
    return r;
}
__device__ __forceinline__ void ffma2(u64t& d, u64t a, u64t b) {
    asm volatile("fma.rn.f32x2 %0, %1, %2, %0;" : "+l"(d) : "l"(a), "l"(b));
}
__device__ __forceinline__ float2 unpk(u64t v) {
    float2 f;
    asm("mov.b64 {%0, %1}, %2;" : "=f"(f.x), "=f"(f.y) : "l"(v));
    return f;
}

// ---------------- fused GEMM + BN-stats (FFMA2, packed fp32x2) ------------------
// out[N,96] = [x|T1|T2][N,288] @ g_Wc[288,96]. BM=128, BK=16, 256 threads.
// Thread tile: 4 rows x 12 cols (= 4x6 packed col-pair accumulators).
#define BM 128
#define BK 16
__global__ __launch_bounds__(256) void k_gemm(const float* __restrict__ x,
                                              float* __restrict__ out) {
    __shared__ u64t  As2[BK][BM];      // 16 KB, dup pairs
    __shared__ float Bs[BK][DF];       // 6 KB
    __shared__ float s_sum[DF], s_sq[DF];

    int tid = threadIdx.x;
    int tr = tid >> 3;          // 0..31 -> rows tr*4 .. +3
    int tc = tid & 7;           // 0..7  -> cols tc*12 .. +11
    int row0 = blockIdx.x * BM;

    if (tid < DF) { s_sum[tid] = 0.f; s_sq[tid] = 0.f; }

    u64t acc[4][6];
#pragma unroll
    for (int i = 0; i < 4; i++)
#pragma unroll
        for (int j = 0; j < 6; j++) acc[i][j] = 0ull;

    const float* bases[3] = { x, g_T1, g_T2 };

    int a_row = tid & 127;
    int a_half = tid >> 7;      // 0 or 1
    int b_kk = tid >> 4;
    int b_c0 = (tid & 15) * 6;

    for (int kc = 0; kc < 18; kc++) {
        const float* A = bases[kc / 6];
        int klocal = (kc % 6) * BK;
        int r = row0 + a_row;

#pragma unroll
        for (int q = 0; q < 2; q++) {
            int kq = (a_half * 2 + q) * 4;
            float4 av = make_float4(0.f, 0.f, 0.f, 0.f);
            if (r < NNODES)
                av = *reinterpret_cast<const float4*>(A + r * DF + klocal + kq);
            As2[kq + 0][a_row] = dup2(av.x);
            As2[kq + 1][a_row] = dup2(av.y);
            As2[kq + 2][a_row] = dup2(av.z);
            As2[kq + 3][a_row] = dup2(av.w);
        }
        {
            const float* Bp = g_Wc + (kc * BK + b_kk) * DF + b_c0;
#pragma unroll
            for (int j = 0; j < 6; j++) Bs[b_kk][b_c0 + j] = Bp[j];
        }
        __syncthreads();

#pragma unroll
        for (int kk = 0; kk < BK; kk++) {
            const ulonglong2* pa =
                reinterpret_cast<const ulonglong2*>(&As2[kk][tr * 4]);
            ulonglong2 A0 = pa[0], A1 = pa[1];
            const ulonglong2* pb =
                reinterpret_cast<const ulonglong2*>(&Bs[kk][tc * 12]);
            ulonglong2 B0 = pb[0], B1 = pb[1], B2 = pb[2];
            u64t a[4] = { A0.x, A0.y, A1.x, A1.y };
            u64t b[6] = { B0.x, B0.y, B1.x, B1.y, B2.x, B2.y };
#pragma unroll
            for (int i = 0; i < 4; i++)
#pragma unroll
                for (int j = 0; j < 6; j++) ffma2(acc[i][j], a[i], b[j]);
        }
        __syncthreads();
    }

    // epilogue: store + per-column stats (invalid rows hold exact zeros)
    float csum[12], csq[12];
#pragma unroll
    for (int j = 0; j < 12; j++) { csum[j] = 0.f; csq[j] = 0.f; }

#pragma unroll
    for (int i = 0; i < 4; i++) {
        int r = row0 + tr * 4 + i;
        float v[12];
#pragma unroll
        for (int j = 0; j < 6; j++) {
            float2 f = unpk(acc[i][j]);
            v[2 * j] = f.x;
            v[2 * j + 1] = f.y;
        }
#pragma unroll
        for (int j = 0; j < 12; j++) { csum[j] += v[j]; csq[j] += v[j] * v[j]; }
        if (r < NNODES) {
            float* op = out + r * DF + tc * 12;
#pragma unroll
            for (int j = 0; j < 3; j++)
                reinterpret_cast<float4*>(op)[j] =
                    make_float4(v[4 * j], v[4 * j + 1], v[4 * j + 2], v[4 * j + 3]);
        }
    }

    // reduce stats: lanes sharing tc within a warp are {tc, tc+8, tc+16, tc+24}
#pragma unroll
    for (int j = 0; j < 12; j++) {
        csum[j] += __shfl_xor_sync(0xffffffffu, csum[j], 8);
        csum[j] += __shfl_xor_sync(0xffffffffu, csum[j], 16);
        csq[j]  += __shfl_xor_sync(0xffffffffu, csq[j], 8);
        csq[j]  += __shfl_xor_sync(0xffffffffu, csq[j], 16);
    }
    __syncthreads();   // s_sum/s_sq init visible
    if ((threadIdx.x & 31) < 8) {
#pragma unroll
        for (int j = 0; j < 12; j++) {
            atomicAdd(&s_sum[tc * 12 + j], csum[j]);
            atomicAdd(&s_sq[tc * 12 + j], csq[j]);
        }
    }
    __syncthreads();
    if (tid < DF) {
        atomicAdd(&g_stats[tid], s_sum[tid]);
        atomicAdd(&g_stats[DF + tid], s_sq[tid]);
    }
}

// ---------------- BN finalize + apply ------------------------------------------
__global__ void k_bnfin(const float* __restrict__ gamma,
                        const float* __restrict__ beta) {
    int c = threadIdx.x;
    if (c >= DF) return;
    float mean = g_stats[c] * (1.0f / NNODES);
    float var  = g_stats[DF + c] * (1.0f / NNODES) - mean * mean;
    float a = gamma[c] * rsqrtf(var + 1e-5f);
    g_ab[c] = a;
    g_ab[DF + c] = beta[c] - mean * a;
}

__global__ void k_bnapply(float* __restrict__ out) {
    int t = blockIdx.x * blockDim.x + threadIdx.x;
    if (t >= NNODES * NF4) return;
    int j = t % NF4;
    int c0 = j * 4;
    float4 v = reinterpret_cast<float4*>(out)[t];
    v.x = v.x * g_ab[c0 + 0] + g_ab[DF + c0 + 0];
    v.y = v.y * g_ab[c0 + 1] + g_ab[DF + c0 + 1];
    v.z = v.z * g_ab[c0 + 2] + g_ab[DF + c0 + 2];
    v.w = v.w * g_ab[c0 + 3] + g_ab[DF + c0 + 3];
    reinterpret_cast<float4*>(out)[t] = v;
}

// ---------------- launch -------------------------------------------------------
extern "C" void kernel_launch(void* const* d_in, const int* in_sizes, int n_in,
                              void* d_out, int out_size) {
    const float* x     = (const float*)d_in[0];
    const int*   ei    = (const int*)  d_in[1];
    const float* W     = (const float*)d_in[2];
    const float* gamma = (const float*)d_in[4];
    const float* beta  = (const float*)d_in[5];
    float* out = (float*)d_out;

    k_init <<<128, 512>>>();
    k_count<<<(NEDGES + 255) / 256, 256>>>(ei);
    k_dis  <<<(NNODES + 255) / 256, 256>>>();

    k_scan_blk<<<NBLK, SBLK>>>();
    k_scan_top<<<1, 128>>>();
    k_scan_add<<<(NNODES + 255) / 256, 256>>>();

    k_fill <<<(NEDGES + 255) / 256, 256>>>(ei);

    const int pullBlocks = (NNODES * 32 + 255) / 256;
    k_pull<<<pullBlocks, 256>>>(0, x);   // T1 = L x
    k_pull<<<pullBlocks, 256>>>(1, x);   // T2 = L T1

    k_wprep<<<(3 * DF * DF + 255) / 256, 256>>>(W);
    k_gemm <<<(NNODES + BM - 1) / BM, 256>>>(x, out);   // + fused BN stats

    k_bnfin  <<<1, DF>>>(gamma, beta);
    k_bnapply<<<(NNODES * NF4 + 255) / 256, 256>>>(out);
}